// round 9
// baseline (speedup 1.0000x reference)
#include <cuda_runtime.h>
#include <math.h>

#define LDA 132
#define LDW 136
#define NT 256
#define MAXROWS (20000*20)

__device__ float g_z[(size_t)MAXROWS*128];
__device__ float g_q[(size_t)MAXROWS*128];
__device__ float g_k[(size_t)MAXROWS*128];
__device__ float g_v[(size_t)MAXROWS*128];
__device__ float g_o[(size_t)MAXROWS*128];
__device__ float g_x[(size_t)MAXROWS*128];

// preconverted tf32 weights
#define W_EW  0
#define W_Q   16384
#define W_K   32768
#define W_V   49152
#define W_QS  65536
#define W_AFC 81920
#define W_F1  98304
#define W_F2  163840
#define W_TOT 229376
__device__ float g_wbuf[W_TOT];

__device__ __forceinline__ float gelu_exact(float x) {
    return 0.5f * x * (1.0f + erff(x * 0.7071067811865475f));
}
__device__ __forceinline__ float to_tf32(float x) {
    unsigned u;
    asm("cvt.rna.tf32.f32 %0, %1;" : "=r"(u) : "f"(x));
    return __uint_as_float(u);
}
__device__ __forceinline__ void mma_tf32(float d[4], const float a[4], const float b[2]) {
    asm volatile(
        "mma.sync.aligned.m16n8k8.row.col.f32.tf32.tf32.f32 "
        "{%0,%1,%2,%3}, {%4,%5,%6,%7}, {%8,%9}, {%0,%1,%2,%3};"
        : "+f"(d[0]), "+f"(d[1]), "+f"(d[2]), "+f"(d[3])
        : "r"(__float_as_uint(a[0])), "r"(__float_as_uint(a[1])),
          "r"(__float_as_uint(a[2])), "r"(__float_as_uint(a[3])),
          "r"(__float_as_uint(b[0])), "r"(__float_as_uint(b[1])));
}

#define ACC_ZERO2(acc) do { _Pragma("unroll") for (int _m=0;_m<2;_m++) _Pragma("unroll") for (int _n=0;_n<4;_n++) { acc[_m][_n][0]=0.f;acc[_m][_n][1]=0.f;acc[_m][_n][2]=0.f;acc[_m][_n][3]=0.f; } } while(0)
#define ACC_ZERO8(acc) do { _Pragma("unroll") for (int _m=0;_m<2;_m++) _Pragma("unroll") for (int _n=0;_n<8;_n++) { acc[_m][_n][0]=0.f;acc[_m][_n][1]=0.f;acc[_m][_n][2]=0.f;acc[_m][_n][3]=0.f; } } while(0)

__device__ __forceinline__ void cpa16(float* dst, const float* src) {
    unsigned u = (unsigned)__cvta_generic_to_shared(dst);
    asm volatile("cp.async.cg.shared.global [%0], [%1], 16;\n" :: "r"(u), "l"(src));
}
#define CP_COMMIT() asm volatile("cp.async.commit_group;\n")
#define CP_WAIT(n)  asm volatile("cp.async.wait_group %0;\n" :: "n"(n))

// stage one 32-row k-chunk of preconverted tf32 W via cp.async
__device__ __forceinline__ void stageWa(float* dst, const float* __restrict__ W,
                                        int ldw, int krow0, int col0, int tid) {
#pragma unroll
    for (int j = 0; j < 4; j++) {
        int idx = tid + j * NT;
        int r = idx >> 5;
        int c4 = (idx & 31) << 2;
        cpa16(dst + r * LDW + c4, W + (size_t)(krow0 + r) * ldw + col0 + c4);
    }
}

// stage 64 rows of activations via cp.async; rows >= rv zero-filled
__device__ __forceinline__ void stageActa(float* sA, const float* __restrict__ g,
                                          long row0, int rv, int tid) {
#pragma unroll
    for (int j = 0; j < 8; j++) {
        int idx = tid + j * NT;
        int r = idx >> 5;
        int c4 = (idx & 31) << 2;
        if (r < rv) cpa16(sA + r * LDA + c4, g + (size_t)(row0 + r) * 128 + c4);
        else *(float4*)(sA + r * LDA + c4) = make_float4(0.f, 0.f, 0.f, 0.f);
    }
    CP_COMMIT();
}

// stage 128 rows of activations via cp.async; rows >= rv zero-filled
__device__ __forceinline__ void stageActa128(float* sA, const float* __restrict__ g,
                                             long row0, int rv, int tid) {
#pragma unroll
    for (int j = 0; j < 16; j++) {
        int idx = tid + j * NT;
        int r = idx >> 5;
        int c4 = (idx & 31) << 2;
        if (r < rv) cpa16(sA + r * LDA + c4, g + (size_t)(row0 + r) * 128 + c4);
        else *(float4*)(sA + r * LDA + c4) = make_float4(0.f, 0.f, 0.f, 0.f);
    }
    CP_COMMIT();
}

// M=64 tile: acc[2][4][4], warp grid 2(M)x4(N), warp tile 32x32
__device__ __forceinline__ void gemm128a(float acc[2][4][4], const float* sAct,
                                         const float* __restrict__ Wg, int ldw, int col0,
                                         float* sWbuf, int tid) {
    const int lane = tid & 31, w = tid >> 5;
    const int mg = w & 1, ng = w >> 1;
    const int qr = lane >> 2, qc = lane & 3;
    stageWa(sWbuf, Wg, ldw, 0, col0, tid);
    CP_COMMIT();
#pragma unroll
    for (int kc = 0; kc < 4; kc++) {
        const float* sw = sWbuf + (kc & 1) * (32 * LDW);
        if (kc < 3) {
            stageWa(sWbuf + ((kc + 1) & 1) * (32 * LDW), Wg, ldw, (kc + 1) * 32, col0, tid);
            CP_COMMIT();
            CP_WAIT(1);
        } else {
            CP_WAIT(0);
        }
        __syncthreads();
#pragma unroll
        for (int ks = 0; ks < 4; ks++) {
            const int k0 = kc * 32 + ks * 8;
            const int kl = ks * 8;
            float af[2][4];
#pragma unroll
            for (int mt = 0; mt < 2; mt++) {
                const float* ap = sAct + ((mg * 2 + mt) * 16 + qr) * LDA + k0 + qc;
                af[mt][0] = ap[0];
                af[mt][1] = ap[8 * LDA];
                af[mt][2] = ap[4];
                af[mt][3] = ap[8 * LDA + 4];
            }
#pragma unroll
            for (int nt = 0; nt < 4; nt++) {
                const float* bp = sw + (kl + qc) * LDW + (ng * 4 + nt) * 8 + qr;
                float bf[2];
                bf[0] = bp[0];
                bf[1] = bp[4 * LDW];
#pragma unroll
                for (int mt = 0; mt < 2; mt++) mma_tf32(acc[mt][nt], af[mt], bf);
            }
        }
        __syncthreads();
    }
}

// M=128 tile: acc[2][8][4], warp grid 4(M)x2(N), warp tile 32x64
__device__ __forceinline__ void gemm128b(float acc[2][8][4], const float* sAct,
                                         const float* __restrict__ Wg, int ldw, int col0,
                                         float* sWbuf, int tid) {
    const int lane = tid & 31, w = tid >> 5;
    const int mg = w >> 1, ng = w & 1;
    const int qr = lane >> 2, qc = lane & 3;
    stageWa(sWbuf, Wg, ldw, 0, col0, tid);
    CP_COMMIT();
#pragma unroll
    for (int kc = 0; kc < 4; kc++) {
        const float* sw = sWbuf + (kc & 1) * (32 * LDW);
        if (kc < 3) {
            stageWa(sWbuf + ((kc + 1) & 1) * (32 * LDW), Wg, ldw, (kc + 1) * 32, col0, tid);
            CP_COMMIT();
            CP_WAIT(1);
        } else {
            CP_WAIT(0);
        }
        __syncthreads();
#pragma unroll
        for (int ks = 0; ks < 4; ks++) {
            const int k0 = kc * 32 + ks * 8;
            const int kl = ks * 8;
            float af[2][4];
#pragma unroll
            for (int mt = 0; mt < 2; mt++) {
                const float* ap = sAct + (mg * 32 + mt * 16 + qr) * LDA + k0 + qc;
                af[mt][0] = ap[0];
                af[mt][1] = ap[8 * LDA];
                af[mt][2] = ap[4];
                af[mt][3] = ap[8 * LDA + 4];
            }
#pragma unroll
            for (int nt = 0; nt < 8; nt++) {
                const float* bp = sw + (kl + qc) * LDW + ng * 64 + nt * 8 + qr;
                float bf[2];
                bf[0] = bp[0];
                bf[1] = bp[4 * LDW];
#pragma unroll
                for (int mt = 0; mt < 2; mt++) mma_tf32(acc[mt][nt], af[mt], bf);
            }
        }
        __syncthreads();
    }
}

// guarded tf32 store for M=128 tile
__device__ __forceinline__ void storeB(float* __restrict__ g, long row0, int rv,
                                       float acc[2][8][4], int tid) {
    const int lane = tid & 31, w = tid >> 5;
    const int mg = w >> 1, ng = w & 1;
    const int qr = lane >> 2, qc = lane & 3;
#pragma unroll
    for (int mt = 0; mt < 2; mt++) {
#pragma unroll
        for (int hh = 0; hh < 2; hh++) {
            int lr = mg * 32 + mt * 16 + qr + hh * 8;
            if (lr < rv) {
#pragma unroll
                for (int nt = 0; nt < 8; nt++) {
                    int c = ng * 64 + nt * 8 + qc * 2;
                    float2 a;
                    a.x = to_tf32(acc[mt][nt][hh * 2]);
                    a.y = to_tf32(acc[mt][nt][hh * 2 + 1]);
                    *(float2*)(g + (size_t)(row0 + lr) * 128 + c) = a;
                }
            }
        }
    }
}

// ------------------- kernel 0: preconvert weights to tf32 -------------------
__global__ void k_prep(const float* __restrict__ e_w, const float* __restrict__ wq,
                       const float* __restrict__ wk, const float* __restrict__ wv,
                       const float* __restrict__ wq_src, const float* __restrict__ afc_w,
                       const float* __restrict__ f_w1, const float* __restrict__ f_w2)
{
    int i = blockIdx.x * 256 + threadIdx.x;
    if (i >= W_TOT) return;
    const float* src; int off;
    if      (i < W_Q)   { src = e_w;    off = W_EW; }
    else if (i < W_K)   { src = wq;     off = W_Q; }
    else if (i < W_V)   { src = wk;     off = W_K; }
    else if (i < W_QS)  { src = wv;     off = W_V; }
    else if (i < W_AFC) { src = wq_src; off = W_QS; }
    else if (i < W_F1)  { src = afc_w;  off = W_AFC; }
    else if (i < W_F2)  { src = f_w1;   off = W_F1; }
    else                { src = f_w2;   off = W_F2; }
    g_wbuf[i] = to_tf32(src[i - off]);
}

// ------------------- kernel 1: z + qkv fused (M=128 tiles) -------------------
__global__ __launch_bounds__(NT, 2)
void k_zqkv(const float* __restrict__ nh, const float* __restrict__ t,
            const float* __restrict__ t_now, const float* __restrict__ ef,
            const float* __restrict__ bfreq, const float* __restrict__ phase,
            const float* __restrict__ e_b, long totrows)
{
    extern __shared__ float sm[];
    float* sA = sm;                      // 128 x LDA, ef then z in-place
    float* sW = sm + 128 * LDA;
    const int tid = threadIdx.x;
    const long row0 = (long)blockIdx.x * 128;
    const int rv = (int)min((long)128, totrows - row0);

    // stage ef (fp32 -> tf32)
#pragma unroll
    for (int j = 0; j < 16; j++) {
        int idx = tid + j * NT;
        int r = idx >> 5;
        int c4 = (idx & 31) << 2;
        float4 v = make_float4(0.f, 0.f, 0.f, 0.f);
        if (r < rv) v = *(const float4*)(ef + (size_t)(row0 + r) * 128 + c4);
        float4 o;
        o.x = to_tf32(v.x); o.y = to_tf32(v.y); o.z = to_tf32(v.z); o.w = to_tf32(v.w);
        *(float4*)(sA + r * LDA + c4) = o;
    }
    __syncthreads();

    float acc[2][8][4];
    ACC_ZERO8(acc);
    gemm128b(acc, sA, g_wbuf + W_EW, 128, 0, sW, tid);
    // (gemm ends with __syncthreads -> safe to overwrite sA)

    const float tn = t_now[0];
    const int lane = tid & 31, w = tid >> 5;
    const int mg = w >> 1, ng = w & 1;
    const int qr = lane >> 2, qc = lane & 3;
#pragma unroll
    for (int mt = 0; mt < 2; mt++) {
#pragma unroll
        for (int hh = 0; hh < 2; hh++) {
            int lr = mg * 32 + mt * 16 + qr + hh * 8;
            long gr = row0 + lr;
            bool ok = (lr < rv);
            float tv = ok ? t[gr] : 0.f;
#pragma unroll
            for (int nt = 0; nt < 8; nt++) {
#pragma unroll
                for (int p = 0; p < 2; p++) {
                    int cc = ng * 64 + nt * 8 + qc * 2 + p;
                    float zv = 0.f;
                    if (ok) {
                        float g = gelu_exact(acc[mt][nt][hh * 2 + p] + e_b[cc]);
                        float te = cosf((tn - tv) * bfreq[cc] + phase[cc]);
                        zv = to_tf32(nh[(size_t)gr * 128 + cc] + g + te);
                        g_z[(size_t)gr * 128 + cc] = zv;
                    }
                    sA[lr * LDA + cc] = zv;
                }
            }
        }
    }
    // first sync inside next gemm orders these writes before any A reads

    ACC_ZERO8(acc); gemm128b(acc, sA, g_wbuf + W_Q, 128, 0, sW, tid); storeB(g_q, row0, rv, acc, tid);
    ACC_ZERO8(acc); gemm128b(acc, sA, g_wbuf + W_K, 128, 0, sW, tid); storeB(g_k, row0, rv, acc, tid);
    ACC_ZERO8(acc); gemm128b(acc, sA, g_wbuf + W_V, 128, 0, sW, tid); storeB(g_v, row0, rv, acc, tid);
}

// ------------------- kernel 2: self_q -------------------
__global__ __launch_bounds__(NT, 2)
void k_selfq(int Ntot)
{
    extern __shared__ float sm[];
    float* sA = sm;
    float* sW = sm + 64 * LDA;
    const int tid = threadIdx.x;
    const int n0 = blockIdx.x * 64;
    const int rv = min(64, Ntot - n0);
#pragma unroll
    for (int j = 0; j < 8; j++) {
        int idx = tid + j * NT;
        int r = idx >> 5;
        int c4 = (idx & 31) << 2;
        if (r < rv) cpa16(sA + r * LDA + c4, g_z + ((size_t)(n0 + r) * 20 + 19) * 128 + c4);
        else *(float4*)(sA + r * LDA + c4) = make_float4(0.f, 0.f, 0.f, 0.f);
    }
    CP_COMMIT();
    float acc[2][4][4];
    ACC_ZERO2(acc);
    gemm128a(acc, sA, g_wbuf + W_QS, 128, 0, sW, tid);
    const int lane = tid & 31, w = tid >> 5;
    const int mg = w & 1, ng = w >> 1;
    const int qr = lane >> 2, qc = lane & 3;
#pragma unroll
    for (int mt = 0; mt < 2; mt++) {
        int r = (mg * 2 + mt) * 16 + qr;
#pragma unroll
        for (int nt = 0; nt < 4; nt++) {
            int c = (ng * 4 + nt) * 8 + qc * 2;
#pragma unroll
            for (int hh = 0; hh < 2; hh++) {
                int rr = r + hh * 8;
                if (rr < rv) {
                    size_t go = ((size_t)(n0 + rr) * 20 + 19) * 128 + c;
                    float2 v;
                    v.x = to_tf32(acc[mt][nt][hh * 2]);
                    v.y = to_tf32(acc[mt][nt][hh * 2 + 1]);
                    *(float2*)(g_q + go) = v;
                    *(float2*)(g_k + go) = v;
                    *(float2*)(g_v + go) = v;
                }
            }
        }
    }
}

// ------------------- kernel 3: attention (conflict-free K/V, q from gmem) ----
#define AHS 36          // head stride in smem (4-byte disjoint bank windows)
#define ARS 144         // row stride = 4*AHS
__global__ __launch_bounds__(NT, 2)
void k_attn(int Ntot)
{
    extern __shared__ float sm[];
    float* sk = sm;                        // [60][144]
    float* sv = sm + 60 * ARS;             // [60][144]
    float* sO = sm + 120 * ARS;            // [60][132]
    const int tid = threadIdx.x;
    const int nb0 = blockIdx.x * 3;
    const int nodes_here = min(3, Ntot - nb0);
    const int rows = nodes_here * 20;
    const size_t gbase = (size_t)nb0 * 20 * 128;

    for (int i = tid; i < rows * 32; i += NT) {
        int r = i >> 5, c4 = (i & 31) << 2;
        int hd = c4 >> 5, ci = c4 & 31;
        *(float4*)(sk + r * ARS + hd * AHS + ci) = *(const float4*)(g_k + gbase + (size_t)r * 128 + c4);
        *(float4*)(sv + r * ARS + hd * AHS + ci) = *(const float4*)(g_v + gbase + (size_t)r * 128 + c4);
    }
    __syncthreads();

    const int node = tid / 80, h = (tid / 20) % 4, qi = tid % 20;
    const bool active = tid < nodes_here * 80;
    float oacc[32];
    if (active) {
        float qreg[32];
        const float* qp = g_q + gbase + (size_t)(node * 20 + qi) * 128 + h * 32;
#pragma unroll
        for (int j = 0; j < 8; j++) {
            float4 v = *(const float4*)(qp + j * 4);
            qreg[4*j] = v.x; qreg[4*j+1] = v.y; qreg[4*j+2] = v.z; qreg[4*j+3] = v.w;
        }
        float p[20];
#pragma unroll
        for (int ki = 0; ki < 20; ki++) {
            const float* kp = sk + (node * 20 + ki) * ARS + h * AHS;
            float s = 0.f;
#pragma unroll
            for (int j = 0; j < 8; j++) {
                float4 kv = *(const float4*)(kp + j * 4);
                s += qreg[4*j] * kv.x + qreg[4*j+1] * kv.y + qreg[4*j+2] * kv.z + qreg[4*j+3] * kv.w;
            }
            p[ki] = s * 0.17677669529663687f;
        }
        float m = p[0];
#pragma unroll
        for (int ki = 1; ki < 20; ki++) m = fmaxf(m, p[ki]);
        float ssum = 0.f;
#pragma unroll
        for (int ki = 0; ki < 20; ki++) { p[ki] = expf(p[ki] - m); ssum += p[ki]; }
        float inv = 1.f / ssum;
#pragma unroll
        for (int j = 0; j < 32; j++) oacc[j] = 0.f;
#pragma unroll
        for (int ki = 0; ki < 20; ki++) {
            float pw = p[ki] * inv;
            const float* vp = sv + (node * 20 + ki) * ARS + h * AHS;
#pragma unroll
            for (int j = 0; j < 8; j++) {
                float4 vv = *(const float4*)(vp + j * 4);
                oacc[4*j]   += pw * vv.x; oacc[4*j+1] += pw * vv.y;
                oacc[4*j+2] += pw * vv.z; oacc[4*j+3] += pw * vv.w;
            }
        }
        float* op = sO + (node * 20 + qi) * 132 + h * 32;
#pragma unroll
        for (int j = 0; j < 8; j++) {
            float4 v;
            v.x = to_tf32(oacc[4*j]);   v.y = to_tf32(oacc[4*j+1]);
            v.z = to_tf32(oacc[4*j+2]); v.w = to_tf32(oacc[4*j+3]);
            *(float4*)(op + j * 4) = v;
        }
    }
    __syncthreads();
    for (int i = tid; i < rows * 32; i += NT) {
        int r = i >> 5, c4 = (i & 31) << 2;
        *(float4*)(g_o + gbase + (size_t)r * 128 + c4) = *(const float4*)(sO + r * 132 + c4);
    }
}

// ------------------- kernel 4: attn_fc + residual + LN -> x (M=128) ----------
__global__ __launch_bounds__(NT, 2)
void k_attnfc(const float* __restrict__ afc_b, const float* __restrict__ aln_g,
              const float* __restrict__ aln_b, long totrows)
{
    extern __shared__ float sm[];
    float* sA = sm;                      // 128 x LDA
    float* sW = sm + 128 * LDA;
    float* scr = sW;                     // reuse after gemm
    const int tid = threadIdx.x;
    const long row0 = (long)blockIdx.x * 128;
    const int rv = (int)min((long)128, totrows - row0);
    stageActa128(sA, g_o, row0, rv, tid);
    float acc[2][8][4];
    ACC_ZERO8(acc);
    gemm128b(acc, sA, g_wbuf + W_AFC, 128, 0, sW, tid);
    {
        const int lane = tid & 31, w = tid >> 5;
        const int mg = w >> 1, ng = w & 1;
        const int qr = lane >> 2, qc = lane & 3;
#pragma unroll
        for (int mt = 0; mt < 2; mt++) {
#pragma unroll
            for (int hh = 0; hh < 2; hh++) {
                int r = mg * 32 + mt * 16 + qr + hh * 8;
#pragma unroll
                for (int nt = 0; nt < 8; nt++) {
                    int c = ng * 64 + nt * 8 + qc * 2;
                    sA[r * LDA + c]     = acc[mt][nt][hh * 2];
                    sA[r * LDA + c + 1] = acc[mt][nt][hh * 2 + 1];
                }
            }
        }
    }
    __syncthreads();
    for (int i = tid; i < 128 * 128; i += NT) {
        int r = i >> 7, d = i & 127;
        if (r < rv) sA[r * LDA + d] += afc_b[d] + g_z[(size_t)(row0 + r) * 128 + d];
    }
    __syncthreads();
    if (tid < 128) {
        float m = 0.f;
#pragma unroll 8
        for (int dd = 0; dd < 128; dd++) m += sA[tid * LDA + ((dd + tid) & 127)];
        m *= (1.0f / 128.0f);
        float v = 0.f;
#pragma unroll 8
        for (int dd = 0; dd < 128; dd++) { float x = sA[tid * LDA + ((dd + tid) & 127)] - m; v += x * x; }
        v *= (1.0f / 128.0f);
        scr[tid] = m;
        scr[128 + tid] = rsqrtf(v + 1e-5f);
    }
    __syncthreads();
    for (int i = tid; i < 128 * 128; i += NT) {
        int r = i >> 7, d = i & 127;
        if (r < rv) {
            float y = (sA[r * LDA + d] - scr[r]) * scr[128 + r] * aln_g[d] + aln_b[d];
            g_x[(size_t)(row0 + r) * 128 + d] = to_tf32(y);
        }
    }
}

// ------------------- kernel 5: FFN + LN + fuse + out -------------------
__global__ __launch_bounds__(NT, 2)
void k_ffn(const float* __restrict__ f_b1, const float* __restrict__ f_b2,
           const float* __restrict__ fln_g, const float* __restrict__ fln_b,
           const float* __restrict__ f2n_w, const float* __restrict__ f2n_b,
           const float* __restrict__ oln_g, const float* __restrict__ oln_b,
           const float* __restrict__ nh, float* __restrict__ out, int Ntot)
{
    extern __shared__ float sm[];
    float* sX = sm;
    float* sH = sX + 64 * LDA;
    float* sW = sH + 64 * LDA;
    float* scr = sW + 2 * 32 * LDW;
    const int tid = threadIdx.x;
    const int nb0 = blockIdx.x * 3;
    const int nodes_here = min(3, Ntot - nb0);
    const int rows_here = nodes_here * 20;
    const long row0 = (long)nb0 * 20;

    stageActa(sX, g_x, row0, rows_here, tid);

    float x2[2][4][4];
    ACC_ZERO2(x2);
    const int lane = tid & 31, w = tid >> 5;
    const int mg = w & 1, ng = w >> 1;
    const int qr = lane >> 2, qc = lane & 3;

    for (int c = 0; c < 4; c++) {
        float acc[2][4][4];
        ACC_ZERO2(acc);
        gemm128a(acc, sX, g_wbuf + W_F1, 512, c * 128, sW, tid);
#pragma unroll
        for (int mt = 0; mt < 2; mt++) {
            int r = (mg * 2 + mt) * 16 + qr;
#pragma unroll
            for (int nt = 0; nt < 4; nt++) {
                int col = (ng * 4 + nt) * 8 + qc * 2;
                float b0 = f_b1[c * 128 + col], b1 = f_b1[c * 128 + col + 1];
                sH[r * LDA + col]           = to_tf32(fmaxf(acc[mt][nt][0] + b0, 0.f));
                sH[r * LDA + col + 1]       = to_tf32(fmaxf(acc[mt][nt][1] + b1, 0.f));
                sH[(r + 8) * LDA + col]     = to_tf32(fmaxf(acc[mt][nt][2] + b0, 0.f));
                sH[(r + 8) * LDA + col + 1] = to_tf32(fmaxf(acc[mt][nt][3] + b1, 0.f));
            }
        }
        __syncthreads();
        gemm128a(x2, sH, g_wbuf + W_F2 + (size_t)c * 128 * 128, 128, 0, sW, tid);
    }

#pragma unroll
    for (int mt = 0; mt < 2; mt++) {
        int r = (mg * 2 + mt) * 16 + qr;
#pragma unroll
        for (int nt = 0; nt < 4; nt++) {
            int col = (ng * 4 + nt) * 8 + qc * 2;
            float b0 = f_b2[col], b1 = f_b2[col + 1];
            sH[r * LDA + col]           = x2[mt][nt][0] + b0 + sX[r * LDA + col];
            sH[r * LDA + col + 1]       = x2[mt][nt][1] + b1 + sX[r * LDA + col + 1];
            sH[(r + 8) * LDA + col]     = x2[mt][nt][2] + b0 + sX[(r + 8) * LDA + col];
            sH[(r + 8) * LDA + col + 1] = x2[mt][nt][3] + b1 + sX[(r + 8) * LDA + col + 1];
        }
    }
    __syncthreads();

    if (tid < rows_here) {
        float m = 0.f;
#pragma unroll 8
        for (int dd = 0; dd < 128; dd++) m += sH[tid * LDA + ((dd + tid) & 127)];
        m *= (1.0f / 128.0f);
        float v = 0.f;
#pragma unroll 8
        for (int dd = 0; dd < 128; dd++) { float x = sH[tid * LDA + ((dd + tid) & 127)] - m; v += x * x; }
        v *= (1.0f / 128.0f);
        scr[tid] = m;
        scr[64 + tid] = rsqrtf(v + 1e-5f);
    }
    __syncthreads();
    for (int i = tid; i < rows_here * 128; i += NT) {
        int r = i >> 7, d = i & 127;
        sH[r * LDA + d] = (sH[r * LDA + d] - scr[r]) * scr[64 + r] * fln_g[d] + fln_b[d];
    }
    __syncthreads();

    float* sNe = scr + 128;
    float* sY  = scr + 512;
    for (int i = tid; i < nodes_here * 128; i += NT) {
        int node = i >> 7, d = i & 127;
        float s = 0.f;
#pragma unroll
        for (int k = 0; k < 19; k++) s += sH[(node * 20 + k) * LDA + d];
        sNe[i] = s * (1.0f / 19.0f);
    }
    __syncthreads();
    for (int idx = tid; idx < nodes_here * 128; idx += NT) {
        int node = idx >> 7, d = idx & 127;
        const float* selfr = sH + (node * 20 + 19) * LDA;
        const float* ne = sNe + node * 128;
        float a = 0.f;
#pragma unroll 4
        for (int e = 0; e < 128; e++) a += selfr[e] * f2n_w[e * 128 + d];
#pragma unroll 4
        for (int e = 0; e < 128; e++) a += ne[e] * f2n_w[(128 + e) * 128 + d];
        float y = gelu_exact(a + f2n_b[d])
                + nh[((size_t)(nb0 + node) * 20 + 19) * 128 + d];
        sY[idx] = y;
    }
    __syncthreads();
    if (tid < nodes_here) {
        float m = 0.f;
        for (int d = 0; d < 128; d++) m += sY[tid * 128 + d];
        m *= (1.0f / 128.0f);
        float v = 0.f;
        for (int d = 0; d < 128; d++) { float x = sY[tid * 128 + d] - m; v += x * x; }
        v *= (1.0f / 128.0f);
        scr[896 + tid] = m;
        scr[900 + tid] = rsqrtf(v + 1e-5f);
    }
    __syncthreads();
    for (int idx = tid; idx < nodes_here * 128; idx += NT) {
        int node = idx >> 7, d = idx & 127;
        float y = (sY[idx] - scr[896 + node]) * scr[900 + node];
        out[(size_t)(nb0 + node) * 128 + d] = y * oln_g[d] + oln_b[d];
    }
}

// ------------------- launch -------------------
#define SM_128  ((128 * LDA + 2 * 32 * LDW) * 4)
#define SM_AB   ((64 * LDA + 2 * 32 * LDW) * 4)
#define SM_ATT  ((120 * ARS + 60 * 132) * 4)
#define SM_F    ((64 * LDA * 2 + 2 * 32 * LDW + 1024) * 4)

extern "C" void kernel_launch(void* const* d_in, const int* in_sizes, int n_in,
                              void* d_out, int out_size) {
    (void)n_in; (void)out_size;
    const float* nh      = (const float*)d_in[0];
    const float* t       = (const float*)d_in[1];
    const float* t_now   = (const float*)d_in[2];
    const float* ef      = (const float*)d_in[3];
    const float* bfreq   = (const float*)d_in[4];
    const float* phase   = (const float*)d_in[5];
    const float* e_w     = (const float*)d_in[6];
    const float* e_b     = (const float*)d_in[7];
    const float* wq      = (const float*)d_in[8];
    const float* wk      = (const float*)d_in[9];
    const float* wv      = (const float*)d_in[10];
    const float* wq_src  = (const float*)d_in[11];
    const float* afc_w   = (const float*)d_in[12];
    const float* afc_b   = (const float*)d_in[13];
    const float* aln_g   = (const float*)d_in[14];
    const float* aln_b   = (const float*)d_in[15];
    const float* f_w1    = (const float*)d_in[16];
    const float* f_b1    = (const float*)d_in[17];
    const float* f_w2    = (const float*)d_in[18];
    const float* f_b2    = (const float*)d_in[19];
    const float* fln_g   = (const float*)d_in[20];
    const float* fln_b   = (const float*)d_in[21];
    const float* f2n_w   = (const float*)d_in[22];
    const float* f2n_b   = (const float*)d_in[23];
    const float* oln_g   = (const float*)d_in[24];
    const float* oln_b   = (const float*)d_in[25];
    float* out = (float*)d_out;

    const int N = in_sizes[0] / 2560;
    const long totrows = (long)N * 20;
    const int gM128 = (int)((totrows + 127) / 128);

    cudaFuncSetAttribute(k_zqkv,   cudaFuncAttributeMaxDynamicSharedMemorySize, SM_128);
    cudaFuncSetAttribute(k_selfq,  cudaFuncAttributeMaxDynamicSharedMemorySize, SM_AB);
    cudaFuncSetAttribute(k_attn,   cudaFuncAttributeMaxDynamicSharedMemorySize, SM_ATT);
    cudaFuncSetAttribute(k_attnfc, cudaFuncAttributeMaxDynamicSharedMemorySize, SM_128);
    cudaFuncSetAttribute(k_ffn,    cudaFuncAttributeMaxDynamicSharedMemorySize, SM_F);

    k_prep<<<(W_TOT + 255) / 256, 256>>>(e_w, wq, wk, wv, wq_src, afc_w, f_w1, f_w2);
    k_zqkv<<<gM128, NT, SM_128>>>(nh, t, t_now, ef, bfreq, phase, e_b, totrows);
    k_selfq<<<(N + 63) / 64, NT, SM_AB>>>(N);
    k_attn<<<(N + 2) / 3, NT, SM_ATT>>>(N);
    k_attnfc<<<gM128, NT, SM_128>>>(afc_b, aln_g, aln_b, totrows);
    k_ffn<<<(N + 2) / 3, NT, SM_F>>>(f_b1, f_b2, fln_g, fln_b,
                                     f2n_w, f2n_b, oln_g, oln_b, nh, out, N);
}

// round 10
// speedup vs baseline: 1.1231x; 1.1231x over previous
#include <cuda_runtime.h>
#include <math.h>

#define LDA 132
#define LDW 136
#define NT 256
#define MAXROWS (20000*20)

__device__ float g_z[(size_t)MAXROWS*128];
__device__ float g_q[(size_t)MAXROWS*128];
__device__ float g_k[(size_t)MAXROWS*128];
__device__ float g_v[(size_t)MAXROWS*128];
__device__ float g_x[(size_t)MAXROWS*128];

// preconverted tf32 weights
#define W_EW  0
#define W_Q   16384
#define W_K   32768
#define W_V   49152
#define W_QS  65536
#define W_AFC 81920
#define W_F1  98304
#define W_F2  163840
#define W_TOT 229376
__device__ float g_wbuf[W_TOT];

__device__ __forceinline__ float gelu_exact(float x) {
    return 0.5f * x * (1.0f + erff(x * 0.7071067811865475f));
}
__device__ __forceinline__ float to_tf32(float x) {
    unsigned u;
    asm("cvt.rna.tf32.f32 %0, %1;" : "=r"(u) : "f"(x));
    return __uint_as_float(u);
}
__device__ __forceinline__ void mma_tf32(float d[4], const float a[4], const float b[2]) {
    asm volatile(
        "mma.sync.aligned.m16n8k8.row.col.f32.tf32.tf32.f32 "
        "{%0,%1,%2,%3}, {%4,%5,%6,%7}, {%8,%9}, {%0,%1,%2,%3};"
        : "+f"(d[0]), "+f"(d[1]), "+f"(d[2]), "+f"(d[3])
        : "r"(__float_as_uint(a[0])), "r"(__float_as_uint(a[1])),
          "r"(__float_as_uint(a[2])), "r"(__float_as_uint(a[3])),
          "r"(__float_as_uint(b[0])), "r"(__float_as_uint(b[1])));
}

#define ACC_ZERO2(acc) do { _Pragma("unroll") for (int _m=0;_m<2;_m++) _Pragma("unroll") for (int _n=0;_n<4;_n++) { acc[_m][_n][0]=0.f;acc[_m][_n][1]=0.f;acc[_m][_n][2]=0.f;acc[_m][_n][3]=0.f; } } while(0)

__device__ __forceinline__ void cpa16(float* dst, const float* src) {
    unsigned u = (unsigned)__cvta_generic_to_shared(dst);
    asm volatile("cp.async.cg.shared.global [%0], [%1], 16;\n" :: "r"(u), "l"(src));
}
#define CP_COMMIT() asm volatile("cp.async.commit_group;\n")
#define CP_WAIT(n)  asm volatile("cp.async.wait_group %0;\n" :: "n"(n))

// stage one 32-row k-chunk of preconverted tf32 W via cp.async
__device__ __forceinline__ void stageWa(float* dst, const float* __restrict__ W,
                                        int ldw, int krow0, int col0, int tid) {
#pragma unroll
    for (int j = 0; j < 4; j++) {
        int idx = tid + j * NT;
        int r = idx >> 5;
        int c4 = (idx & 31) << 2;
        cpa16(dst + r * LDW + c4, W + (size_t)(krow0 + r) * ldw + col0 + c4);
    }
}

// stage 64 rows of activations via cp.async; rows >= rv zero-filled
__device__ __forceinline__ void stageActa(float* sA, const float* __restrict__ g,
                                          long row0, int rv, int tid) {
#pragma unroll
    for (int j = 0; j < 8; j++) {
        int idx = tid + j * NT;
        int r = idx >> 5;
        int c4 = (idx & 31) << 2;
        if (r < rv) cpa16(sA + r * LDA + c4, g + (size_t)(row0 + r) * 128 + c4);
        else *(float4*)(sA + r * LDA + c4) = make_float4(0.f, 0.f, 0.f, 0.f);
    }
    CP_COMMIT();
}

// M=64 tile: acc[2][4][4], warp grid 2(M)x4(N), warp tile 32x32
__device__ __forceinline__ void gemm128a(float acc[2][4][4], const float* sAct,
                                         const float* __restrict__ Wg, int ldw, int col0,
                                         float* sWbuf, int tid) {
    const int lane = tid & 31, w = tid >> 5;
    const int mg = w & 1, ng = w >> 1;
    const int qr = lane >> 2, qc = lane & 3;
    stageWa(sWbuf, Wg, ldw, 0, col0, tid);
    CP_COMMIT();
#pragma unroll
    for (int kc = 0; kc < 4; kc++) {
        const float* sw = sWbuf + (kc & 1) * (32 * LDW);
        if (kc < 3) {
            stageWa(sWbuf + ((kc + 1) & 1) * (32 * LDW), Wg, ldw, (kc + 1) * 32, col0, tid);
            CP_COMMIT();
            CP_WAIT(1);
        } else {
            CP_WAIT(0);
        }
        __syncthreads();
#pragma unroll
        for (int ks = 0; ks < 4; ks++) {
            const int k0 = kc * 32 + ks * 8;
            const int kl = ks * 8;
            float af[2][4];
#pragma unroll
            for (int mt = 0; mt < 2; mt++) {
                const float* ap = sAct + ((mg * 2 + mt) * 16 + qr) * LDA + k0 + qc;
                af[mt][0] = ap[0];
                af[mt][1] = ap[8 * LDA];
                af[mt][2] = ap[4];
                af[mt][3] = ap[8 * LDA + 4];
            }
#pragma unroll
            for (int nt = 0; nt < 4; nt++) {
                const float* bp = sw + (kl + qc) * LDW + (ng * 4 + nt) * 8 + qr;
                float bf[2];
                bf[0] = bp[0];
                bf[1] = bp[4 * LDW];
#pragma unroll
                for (int mt = 0; mt < 2; mt++) mma_tf32(acc[mt][nt], af[mt], bf);
            }
        }
        __syncthreads();
    }
}

__device__ __forceinline__ void store_direct(float* __restrict__ g, long row0,
                                             float acc[2][4][4], int tid) {
    const int lane = tid & 31, w = tid >> 5;
    const int mg = w & 1, ng = w >> 1;
    const int qr = lane >> 2, qc = lane & 3;
#pragma unroll
    for (int mt = 0; mt < 2; mt++) {
        long r = row0 + (mg * 2 + mt) * 16 + qr;
#pragma unroll
        for (int nt = 0; nt < 4; nt++) {
            int c = (ng * 4 + nt) * 8 + qc * 2;
            float2 a0; a0.x = to_tf32(acc[mt][nt][0]); a0.y = to_tf32(acc[mt][nt][1]);
            float2 a1; a1.x = to_tf32(acc[mt][nt][2]); a1.y = to_tf32(acc[mt][nt][3]);
            *(float2*)(g + (size_t)r * 128 + c) = a0;
            *(float2*)(g + (size_t)(r + 8) * 128 + c) = a1;
        }
    }
}

// ------------------- kernel 0: preconvert weights to tf32 -------------------
__global__ void k_prep(const float* __restrict__ e_w, const float* __restrict__ wq,
                       const float* __restrict__ wk, const float* __restrict__ wv,
                       const float* __restrict__ wq_src, const float* __restrict__ afc_w,
                       const float* __restrict__ f_w1, const float* __restrict__ f_w2)
{
    int i = blockIdx.x * 256 + threadIdx.x;
    if (i >= W_TOT) return;
    const float* src; int off;
    if      (i < W_Q)   { src = e_w;    off = W_EW; }
    else if (i < W_K)   { src = wq;     off = W_Q; }
    else if (i < W_V)   { src = wk;     off = W_K; }
    else if (i < W_QS)  { src = wv;     off = W_V; }
    else if (i < W_AFC) { src = wq_src; off = W_QS; }
    else if (i < W_F1)  { src = afc_w;  off = W_AFC; }
    else if (i < W_F2)  { src = f_w1;   off = W_F1; }
    else                { src = f_w2;   off = W_F2; }
    g_wbuf[i] = to_tf32(src[i - off]);
}

// ------------------- kernel 1: z + qkv fused (M=64 tiles) -------------------
__global__ __launch_bounds__(NT, 2)
void k_zqkv(const float* __restrict__ nh, const float* __restrict__ t,
            const float* __restrict__ t_now, const float* __restrict__ ef,
            const float* __restrict__ bfreq, const float* __restrict__ phase,
            const float* __restrict__ e_b, long totrows)
{
    extern __shared__ float sm[];
    float* sA = sm;
    float* sZ = sm + 64 * LDA;
    float* sW = sZ + 64 * LDA;
    const int tid = threadIdx.x;
    const long row0 = (long)blockIdx.x * 64;
    const int rv = (int)min((long)64, totrows - row0);

#pragma unroll
    for (int j = 0; j < 8; j++) {
        int idx = tid + j * NT;
        int r = idx >> 5;
        int c4 = (idx & 31) << 2;
        float4 v = make_float4(0.f, 0.f, 0.f, 0.f);
        if (r < rv) v = *(const float4*)(ef + (size_t)(row0 + r) * 128 + c4);
        float4 o;
        o.x = to_tf32(v.x); o.y = to_tf32(v.y); o.z = to_tf32(v.z); o.w = to_tf32(v.w);
        *(float4*)(sA + r * LDA + c4) = o;
    }
    __syncthreads();

    float acc[2][4][4];
    ACC_ZERO2(acc);
    gemm128a(acc, sA, g_wbuf + W_EW, 128, 0, sW, tid);

    const float tn = t_now[0];
    const int lane = tid & 31, w = tid >> 5;
    const int mg = w & 1, ng = w >> 1;
    const int qr = lane >> 2, qc = lane & 3;
#pragma unroll
    for (int mt = 0; mt < 2; mt++) {
        int lr0 = (mg * 2 + mt) * 16 + qr;
#pragma unroll
        for (int hh = 0; hh < 2; hh++) {
            int lr = lr0 + hh * 8;
            long gr = row0 + lr;
            bool ok = (lr < rv);
            float tv = ok ? t[gr] : 0.f;
#pragma unroll
            for (int nt = 0; nt < 4; nt++) {
                int c = (ng * 4 + nt) * 8 + qc * 2;
#pragma unroll
                for (int p = 0; p < 2; p++) {
                    int cc = c + p;
                    float zv = 0.f;
                    if (ok) {
                        float g = gelu_exact(acc[mt][nt][hh * 2 + p] + e_b[cc]);
                        float te = cosf((tn - tv) * bfreq[cc] + phase[cc]);
                        zv = to_tf32(nh[(size_t)gr * 128 + cc] + g + te);
                        g_z[(size_t)gr * 128 + cc] = zv;
                    }
                    sZ[lr * LDA + cc] = zv;
                }
            }
        }
    }
    __syncthreads();

    ACC_ZERO2(acc); gemm128a(acc, sZ, g_wbuf + W_Q, 128, 0, sW, tid);
    if (rv == 64) store_direct(g_q, row0, acc, tid);
    else {
#pragma unroll
        for (int mt = 0; mt < 2; mt++) {
            int lr0 = (mg * 2 + mt) * 16 + qr;
#pragma unroll
            for (int hh = 0; hh < 2; hh++) {
                int lr = lr0 + hh * 8;
                if (lr < rv)
#pragma unroll
                    for (int nt = 0; nt < 4; nt++) {
                        int c = (ng * 4 + nt) * 8 + qc * 2;
                        float2 a; a.x = to_tf32(acc[mt][nt][hh*2]); a.y = to_tf32(acc[mt][nt][hh*2+1]);
                        *(float2*)(g_q + (size_t)(row0 + lr) * 128 + c) = a;
                    }
            }
        }
    }
    ACC_ZERO2(acc); gemm128a(acc, sZ, g_wbuf + W_K, 128, 0, sW, tid);
    if (rv == 64) store_direct(g_k, row0, acc, tid);
    ACC_ZERO2(acc); gemm128a(acc, sZ, g_wbuf + W_V, 128, 0, sW, tid);
    if (rv == 64) store_direct(g_v, row0, acc, tid);
}

// ------------------- kernel 2: self_q -------------------
__global__ __launch_bounds__(NT, 2)
void k_selfq(int Ntot)
{
    extern __shared__ float sm[];
    float* sA = sm;
    float* sW = sm + 64 * LDA;
    const int tid = threadIdx.x;
    const int n0 = blockIdx.x * 64;
    const int rv = min(64, Ntot - n0);
#pragma unroll
    for (int j = 0; j < 8; j++) {
        int idx = tid + j * NT;
        int r = idx >> 5;
        int c4 = (idx & 31) << 2;
        if (r < rv) cpa16(sA + r * LDA + c4, g_z + ((size_t)(n0 + r) * 20 + 19) * 128 + c4);
        else *(float4*)(sA + r * LDA + c4) = make_float4(0.f, 0.f, 0.f, 0.f);
    }
    CP_COMMIT();
    float acc[2][4][4];
    ACC_ZERO2(acc);
    gemm128a(acc, sA, g_wbuf + W_QS, 128, 0, sW, tid);
    const int lane = tid & 31, w = tid >> 5;
    const int mg = w & 1, ng = w >> 1;
    const int qr = lane >> 2, qc = lane & 3;
#pragma unroll
    for (int mt = 0; mt < 2; mt++) {
        int r = (mg * 2 + mt) * 16 + qr;
#pragma unroll
        for (int nt = 0; nt < 4; nt++) {
            int c = (ng * 4 + nt) * 8 + qc * 2;
#pragma unroll
            for (int hh = 0; hh < 2; hh++) {
                int rr = r + hh * 8;
                if (rr < rv) {
                    size_t go = ((size_t)(n0 + rr) * 20 + 19) * 128 + c;
                    float2 v;
                    v.x = to_tf32(acc[mt][nt][hh * 2]);
                    v.y = to_tf32(acc[mt][nt][hh * 2 + 1]);
                    *(float2*)(g_q + go) = v;
                    *(float2*)(g_k + go) = v;
                    *(float2*)(g_v + go) = v;
                }
            }
        }
    }
}

// ------------------- kernel 3: attention + attn_fc + residual + LN -> x ------
#define AHS 36
#define ARS 144
__global__ __launch_bounds__(NT, 2)
void k_attn_fc(const float* __restrict__ afc_b, const float* __restrict__ aln_g,
               const float* __restrict__ aln_b, int Ntot)
{
    extern __shared__ float sm[];
    float* sK = sm;                        // [60][144]; later aliased as sO [64][132]
    float* sV = sm + 60 * ARS;             // [60][144]; later aliased as scr
    float* sW = sm + 120 * ARS;            // 2*32*LDW
    const int tid = threadIdx.x;
    const int nb0 = blockIdx.x * 3;
    const int nodes_here = min(3, Ntot - nb0);
    const int rows = nodes_here * 20;
    const long row0 = (long)nb0 * 20;
    const size_t gbase = (size_t)row0 * 128;

    for (int i = tid; i < rows * 32; i += NT) {
        int r = i >> 5, c4 = (i & 31) << 2;
        int hd = c4 >> 5, ci = c4 & 31;
        *(float4*)(sK + r * ARS + hd * AHS + ci) = *(const float4*)(g_k + gbase + (size_t)r * 128 + c4);
        *(float4*)(sV + r * ARS + hd * AHS + ci) = *(const float4*)(g_v + gbase + (size_t)r * 128 + c4);
    }
    __syncthreads();

    const int node = tid / 80, h = (tid / 20) % 4, qi = tid % 20;
    const bool active = tid < nodes_here * 80;
    float oacc[32];
    if (active) {
        float qreg[32];
        const float* qp = g_q + gbase + (size_t)(node * 20 + qi) * 128 + h * 32;
#pragma unroll
        for (int j = 0; j < 8; j++) {
            float4 v = *(const float4*)(qp + j * 4);
            qreg[4*j] = v.x; qreg[4*j+1] = v.y; qreg[4*j+2] = v.z; qreg[4*j+3] = v.w;
        }
        float p[20];
#pragma unroll
        for (int ki = 0; ki < 20; ki++) {
            const float* kp = sK + (node * 20 + ki) * ARS + h * AHS;
            float s = 0.f;
#pragma unroll
            for (int j = 0; j < 8; j++) {
                float4 kv = *(const float4*)(kp + j * 4);
                s += qreg[4*j] * kv.x + qreg[4*j+1] * kv.y + qreg[4*j+2] * kv.z + qreg[4*j+3] * kv.w;
            }
            p[ki] = s * 0.17677669529663687f;
        }
        float m = p[0];
#pragma unroll
        for (int ki = 1; ki < 20; ki++) m = fmaxf(m, p[ki]);
        float ssum = 0.f;
#pragma unroll
        for (int ki = 0; ki < 20; ki++) { p[ki] = expf(p[ki] - m); ssum += p[ki]; }
        float inv = 1.f / ssum;
#pragma unroll
        for (int j = 0; j < 32; j++) oacc[j] = 0.f;
#pragma unroll
        for (int ki = 0; ki < 20; ki++) {
            float pw = p[ki] * inv;
            const float* vp = sV + (node * 20 + ki) * ARS + h * AHS;
#pragma unroll
            for (int j = 0; j < 8; j++) {
                float4 vv = *(const float4*)(vp + j * 4);
                oacc[4*j]   += pw * vv.x; oacc[4*j+1] += pw * vv.y;
                oacc[4*j+2] += pw * vv.z; oacc[4*j+3] += pw * vv.w;
            }
        }
    }
    __syncthreads();   // all K/V reads done; safe to alias

    // O (tf32) -> sO aliasing sK, stride LDA; zero pad rows for the GEMM
    float* sO = sK;
    if (active) {
        float* op = sO + (node * 20 + qi) * LDA + h * 32;
#pragma unroll
        for (int j = 0; j < 8; j++) {
            float4 v;
            v.x = to_tf32(oacc[4*j]);   v.y = to_tf32(oacc[4*j+1]);
            v.z = to_tf32(oacc[4*j+2]); v.w = to_tf32(oacc[4*j+3]);
            *(float4*)(op + j * 4) = v;
        }
    }
    for (int i = tid; i < (64 - rows) * LDA; i += NT) sO[rows * LDA + i] = 0.f;
    __syncthreads();

    // O @ afc_w
    float acc[2][4][4];
    ACC_ZERO2(acc);
    gemm128a(acc, sO, g_wbuf + W_AFC, 128, 0, sW, tid);

    // acc back into sO
    {
        const int lane = tid & 31, w = tid >> 5;
        const int mg = w & 1, ng = w >> 1;
        const int qr = lane >> 2, qc = lane & 3;
#pragma unroll
        for (int mt = 0; mt < 2; mt++) {
            int r = (mg * 2 + mt) * 16 + qr;
#pragma unroll
            for (int nt = 0; nt < 4; nt++) {
                int c = (ng * 4 + nt) * 8 + qc * 2;
                sO[r * LDA + c]           = acc[mt][nt][0];
                sO[r * LDA + c + 1]       = acc[mt][nt][1];
                sO[(r + 8) * LDA + c]     = acc[mt][nt][2];
                sO[(r + 8) * LDA + c + 1] = acc[mt][nt][3];
            }
        }
    }
    __syncthreads();

    // + afc_b + z residual
    for (int i = tid; i < 64 * 128; i += NT) {
        int r = i >> 7, d = i & 127;
        if (r < rows) sO[r * LDA + d] += afc_b[d] + g_z[gbase + (size_t)r * 128 + d];
    }
    __syncthreads();

    // LN -> g_x (tf32)
    float* scr = sV;
    if (tid < rows) {
        float m = 0.f;
#pragma unroll 8
        for (int dd = 0; dd < 128; dd++) m += sO[tid * LDA + ((dd + tid) & 127)];
        m *= (1.0f / 128.0f);
        float v = 0.f;
#pragma unroll 8
        for (int dd = 0; dd < 128; dd++) { float x = sO[tid * LDA + ((dd + tid) & 127)] - m; v += x * x; }
        v *= (1.0f / 128.0f);
        scr[tid] = m;
        scr[64 + tid] = rsqrtf(v + 1e-5f);
    }
    __syncthreads();
    for (int i = tid; i < 64 * 128; i += NT) {
        int r = i >> 7, d = i & 127;
        if (r < rows) {
            float y = (sO[r * LDA + d] - scr[r]) * scr[64 + r] * aln_g[d] + aln_b[d];
            g_x[gbase + (size_t)r * 128 + d] = to_tf32(y);
        }
    }
}

// ------------------- kernel 4: FFN + LN + fuse + out -------------------
__global__ __launch_bounds__(NT, 2)
void k_ffn(const float* __restrict__ f_b1, const float* __restrict__ f_b2,
           const float* __restrict__ fln_g, const float* __restrict__ fln_b,
           const float* __restrict__ f2n_w, const float* __restrict__ f2n_b,
           const float* __restrict__ oln_g, const float* __restrict__ oln_b,
           const float* __restrict__ nh, float* __restrict__ out, int Ntot)
{
    extern __shared__ float sm[];
    float* sX = sm;
    float* sH = sX + 64 * LDA;
    float* sW = sH + 64 * LDA;
    float* scr = sW + 2 * 32 * LDW;
    const int tid = threadIdx.x;
    const int nb0 = blockIdx.x * 3;
    const int nodes_here = min(3, Ntot - nb0);
    const int rows_here = nodes_here * 20;
    const long row0 = (long)nb0 * 20;

    stageActa(sX, g_x, row0, rows_here, tid);

    float x2[2][4][4];
    ACC_ZERO2(x2);
    const int lane = tid & 31, w = tid >> 5;
    const int mg = w & 1, ng = w >> 1;
    const int qr = lane >> 2, qc = lane & 3;

    for (int c = 0; c < 4; c++) {
        float acc[2][4][4];
        ACC_ZERO2(acc);
        gemm128a(acc, sX, g_wbuf + W_F1, 512, c * 128, sW, tid);
#pragma unroll
        for (int mt = 0; mt < 2; mt++) {
            int r = (mg * 2 + mt) * 16 + qr;
#pragma unroll
            for (int nt = 0; nt < 4; nt++) {
                int col = (ng * 4 + nt) * 8 + qc * 2;
                float b0 = f_b1[c * 128 + col], b1 = f_b1[c * 128 + col + 1];
                sH[r * LDA + col]           = to_tf32(fmaxf(acc[mt][nt][0] + b0, 0.f));
                sH[r * LDA + col + 1]       = to_tf32(fmaxf(acc[mt][nt][1] + b1, 0.f));
                sH[(r + 8) * LDA + col]     = to_tf32(fmaxf(acc[mt][nt][2] + b0, 0.f));
                sH[(r + 8) * LDA + col + 1] = to_tf32(fmaxf(acc[mt][nt][3] + b1, 0.f));
            }
        }
        __syncthreads();
        gemm128a(x2, sH, g_wbuf + W_F2 + (size_t)c * 128 * 128, 128, 0, sW, tid);
    }

#pragma unroll
    for (int mt = 0; mt < 2; mt++) {
        int r = (mg * 2 + mt) * 16 + qr;
#pragma unroll
        for (int nt = 0; nt < 4; nt++) {
            int col = (ng * 4 + nt) * 8 + qc * 2;
            float b0 = f_b2[col], b1 = f_b2[col + 1];
            sH[r * LDA + col]           = x2[mt][nt][0] + b0 + sX[r * LDA + col];
            sH[r * LDA + col + 1]       = x2[mt][nt][1] + b1 + sX[r * LDA + col + 1];
            sH[(r + 8) * LDA + col]     = x2[mt][nt][2] + b0 + sX[(r + 8) * LDA + col];
            sH[(r + 8) * LDA + col + 1] = x2[mt][nt][3] + b1 + sX[(r + 8) * LDA + col + 1];
        }
    }
    __syncthreads();

    if (tid < rows_here) {
        float m = 0.f;
#pragma unroll 8
        for (int dd = 0; dd < 128; dd++) m += sH[tid * LDA + ((dd + tid) & 127)];
        m *= (1.0f / 128.0f);
        float v = 0.f;
#pragma unroll 8
        for (int dd = 0; dd < 128; dd++) { float x = sH[tid * LDA + ((dd + tid) & 127)] - m; v += x * x; }
        v *= (1.0f / 128.0f);
        scr[tid] = m;
        scr[64 + tid] = rsqrtf(v + 1e-5f);
    }
    __syncthreads();
    for (int i = tid; i < rows_here * 128; i += NT) {
        int r = i >> 7, d = i & 127;
        sH[r * LDA + d] = (sH[r * LDA + d] - scr[r]) * scr[64 + r] * fln_g[d] + fln_b[d];
    }
    __syncthreads();

    float* sNe = scr + 128;
    float* sY  = scr + 512;
    for (int i = tid; i < nodes_here * 128; i += NT) {
        int node = i >> 7, d = i & 127;
        float s = 0.f;
#pragma unroll
        for (int k = 0; k < 19; k++) s += sH[(node * 20 + k) * LDA + d];
        sNe[i] = s * (1.0f / 19.0f);
    }
    __syncthreads();
    for (int idx = tid; idx < nodes_here * 128; idx += NT) {
        int node = idx >> 7, d = idx & 127;
        const float* selfr = sH + (node * 20 + 19) * LDA;
        const float* ne = sNe + node * 128;
        float a = 0.f;
#pragma unroll 4
        for (int e = 0; e < 128; e++) a += selfr[e] * f2n_w[e * 128 + d];
#pragma unroll 4
        for (int e = 0; e < 128; e++) a += ne[e] * f2n_w[(128 + e) * 128 + d];
        float y = gelu_exact(a + f2n_b[d])
                + nh[((size_t)(nb0 + node) * 20 + 19) * 128 + d];
        sY[idx] = y;
    }
    __syncthreads();
    if (tid < nodes_here) {
        float m = 0.f;
        for (int d = 0; d < 128; d++) m += sY[tid * 128 + d];
        m *= (1.0f / 128.0f);
        float v = 0.f;
        for (int d = 0; d < 128; d++) { float x = sY[tid * 128 + d] - m; v += x * x; }
        v *= (1.0f / 128.0f);
        scr[896 + tid] = m;
        scr[900 + tid] = rsqrtf(v + 1e-5f);
    }
    __syncthreads();
    for (int idx = tid; idx < nodes_here * 128; idx += NT) {
        int node = idx >> 7, d = idx & 127;
        float y = (sY[idx] - scr[896 + node]) * scr[900 + node];
        out[(size_t)(nb0 + node) * 128 + d] = y * oln_g[d] + oln_b[d];
    }
}

// ------------------- launch -------------------
#define SM_ZQKV ((2 * 64 * LDA + 2 * 32 * LDW) * 4)
#define SM_AB   ((64 * LDA + 2 * 32 * LDW) * 4)
#define SM_FUSE ((120 * ARS + 2 * 32 * LDW) * 4)
#define SM_F    ((64 * LDA * 2 + 2 * 32 * LDW + 1024) * 4)

extern "C" void kernel_launch(void* const* d_in, const int* in_sizes, int n_in,
                              void* d_out, int out_size) {
    (void)n_in; (void)out_size;
    const float* nh      = (const float*)d_in[0];
    const float* t       = (const float*)d_in[1];
    const float* t_now   = (const float*)d_in[2];
    const float* ef      = (const float*)d_in[3];
    const float* bfreq   = (const float*)d_in[4];
    const float* phase   = (const float*)d_in[5];
    const float* e_w     = (const float*)d_in[6];
    const float* e_b     = (const float*)d_in[7];
    const float* wq      = (const float*)d_in[8];
    const float* wk      = (const float*)d_in[9];
    const float* wv      = (const float*)d_in[10];
    const float* wq_src  = (const float*)d_in[11];
    const float* afc_w   = (const float*)d_in[12];
    const float* afc_b   = (const float*)d_in[13];
    const float* aln_g   = (const float*)d_in[14];
    const float* aln_b   = (const float*)d_in[15];
    const float* f_w1    = (const float*)d_in[16];
    const float* f_b1    = (const float*)d_in[17];
    const float* f_w2    = (const float*)d_in[18];
    const float* f_b2    = (const float*)d_in[19];
    const float* fln_g   = (const float*)d_in[20];
    const float* fln_b   = (const float*)d_in[21];
    const float* f2n_w   = (const float*)d_in[22];
    const float* f2n_b   = (const float*)d_in[23];
    const float* oln_g   = (const float*)d_in[24];
    const float* oln_b   = (const float*)d_in[25];
    float* out = (float*)d_out;

    const int N = in_sizes[0] / 2560;
    const long totrows = (long)N * 20;
    const int gM = (int)((totrows + 63) / 64);

    cudaFuncSetAttribute(k_zqkv,    cudaFuncAttributeMaxDynamicSharedMemorySize, SM_ZQKV);
    cudaFuncSetAttribute(k_selfq,   cudaFuncAttributeMaxDynamicSharedMemorySize, SM_AB);
    cudaFuncSetAttribute(k_attn_fc, cudaFuncAttributeMaxDynamicSharedMemorySize, SM_FUSE);
    cudaFuncSetAttribute(k_ffn,     cudaFuncAttributeMaxDynamicSharedMemorySize, SM_F);

    k_prep<<<(W_TOT + 255) / 256, 256>>>(e_w, wq, wk, wv, wq_src, afc_w, f_w1, f_w2);
    k_zqkv<<<gM, NT, SM_ZQKV>>>(nh, t, t_now, ef, bfreq, phase, e_b, totrows);
    k_selfq<<<(N + 63) / 64, NT, SM_AB>>>(N);
    k_attn_fc<<<(N + 2) / 3, NT, SM_FUSE>>>(afc_b, aln_g, aln_b, N);
    k_ffn<<<(N + 2) / 3, NT, SM_F>>>(f_b1, f_b2, fln_g, fln_b,
                                     f2n_w, f2n_b, oln_g, oln_b, nh, out, N);
}

// round 11
// speedup vs baseline: 1.1528x; 1.0264x over previous
#include <cuda_runtime.h>
#include <math.h>

#define LDA 132
#define NT 256
#define WCH 4096      // floats per packed 32-k weight chunk
#define MAXROWS (20000*20)

__device__ float g_z[(size_t)MAXROWS*128];
__device__ float g_q[(size_t)MAXROWS*128];
__device__ float g_k[(size_t)MAXROWS*128];
__device__ float g_v[(size_t)MAXROWS*128];
__device__ float g_x[(size_t)MAXROWS*128];

// fragment-packed tf32 weights
#define W_EW  0
#define W_Q   16384
#define W_K   32768
#define W_V   49152
#define W_QS  65536
#define W_AFC 81920
#define W_F1  98304
#define W_F2  163840
#define W_TOT 229376
__device__ float g_wbuf[W_TOT];

__device__ __forceinline__ float gelu_exact(float x) {
    return 0.5f * x * (1.0f + erff(x * 0.7071067811865475f));
}
__device__ __forceinline__ float to_tf32(float x) {
    unsigned u;
    asm("cvt.rna.tf32.f32 %0, %1;" : "=r"(u) : "f"(x));
    return __uint_as_float(u);
}
__device__ __forceinline__ void mma_tf32(float d[4], const float a[4], const float b[2]) {
    asm volatile(
        "mma.sync.aligned.m16n8k8.row.col.f32.tf32.tf32.f32 "
        "{%0,%1,%2,%3}, {%4,%5,%6,%7}, {%8,%9}, {%0,%1,%2,%3};"
        : "+f"(d[0]), "+f"(d[1]), "+f"(d[2]), "+f"(d[3])
        : "r"(__float_as_uint(a[0])), "r"(__float_as_uint(a[1])),
          "r"(__float_as_uint(a[2])), "r"(__float_as_uint(a[3])),
          "r"(__float_as_uint(b[0])), "r"(__float_as_uint(b[1])));
}

#define ACC_ZERO2(acc) do { _Pragma("unroll") for (int _m=0;_m<2;_m++) _Pragma("unroll") for (int _n=0;_n<4;_n++) { acc[_m][_n][0]=0.f;acc[_m][_n][1]=0.f;acc[_m][_n][2]=0.f;acc[_m][_n][3]=0.f; } } while(0)

__device__ __forceinline__ void cpa16(float* dst, const float* src) {
    unsigned u = (unsigned)__cvta_generic_to_shared(dst);
    asm volatile("cp.async.cg.shared.global [%0], [%1], 16;\n" :: "r"(u), "l"(src));
}
#define CP_COMMIT() asm volatile("cp.async.commit_group;\n")
#define CP_WAIT(n)  asm volatile("cp.async.wait_group %0;\n" :: "n"(n))

// stage one packed 32-k chunk (4096 floats, contiguous) via cp.async
__device__ __forceinline__ void stageWp(float* dst, const float* __restrict__ W,
                                        int kc, int tid) {
#pragma unroll
    for (int j = 0; j < 4; j++) {
        int idx = (tid + j * NT) << 2;
        cpa16(dst + idx, W + kc * WCH + idx);
    }
}

// stage 64 rows of activations via cp.async; rows >= rv zero-filled
__device__ __forceinline__ void stageActa(float* sA, const float* __restrict__ g,
                                          long row0, int rv, int tid) {
#pragma unroll
    for (int j = 0; j < 8; j++) {
        int idx = tid + j * NT;
        int r = idx >> 5;
        int c4 = (idx & 31) << 2;
        if (r < rv) cpa16(sA + r * LDA + c4, g + (size_t)(row0 + r) * 128 + c4);
        else *(float4*)(sA + r * LDA + c4) = make_float4(0.f, 0.f, 0.f, 0.f);
    }
    CP_COMMIT();
}

// M=64 tile GEMM on fragment-packed weights: acc[2][4][4], warp grid 2(M)x4(N)
__device__ __forceinline__ void gemm128p(float acc[2][4][4], const float* sAct,
                                         const float* __restrict__ Wg,
                                         float* sWbuf, int tid) {
    const int lane = tid & 31, w = tid >> 5;
    const int mg = w & 1, ng = w >> 1;
    const int qr = lane >> 2, qc = lane & 3;
    stageWp(sWbuf, Wg, 0, tid);
    CP_COMMIT();
#pragma unroll
    for (int kc = 0; kc < 4; kc++) {
        const float* sw = sWbuf + (kc & 1) * WCH;
        if (kc < 3) {
            stageWp(sWbuf + ((kc + 1) & 1) * WCH, Wg, kc + 1, tid);
            CP_COMMIT();
            CP_WAIT(1);
        } else {
            CP_WAIT(0);
        }
        __syncthreads();
#pragma unroll
        for (int ks2 = 0; ks2 < 2; ks2++) {
            float4 bf4[4];
#pragma unroll
            for (int nt = 0; nt < 4; nt++) {
                int n = (ng * 4 + nt) * 8 + qr;
                bf4[nt] = *(const float4*)(sw + ks2 * 2048 + n * 16 + qc * 4);
            }
#pragma unroll
            for (int sub = 0; sub < 2; sub++) {
                const int k0 = kc * 32 + ks2 * 16 + sub * 8;
                float af[2][4];
#pragma unroll
                for (int mt = 0; mt < 2; mt++) {
                    const float* ap = sAct + ((mg * 2 + mt) * 16 + qr) * LDA + k0 + qc;
                    af[mt][0] = ap[0];
                    af[mt][1] = ap[8 * LDA];
                    af[mt][2] = ap[4];
                    af[mt][3] = ap[8 * LDA + 4];
                }
#pragma unroll
                for (int nt = 0; nt < 4; nt++) {
                    float b2[2];
                    b2[0] = sub ? bf4[nt].z : bf4[nt].x;
                    b2[1] = sub ? bf4[nt].w : bf4[nt].y;
                    mma_tf32(acc[0][nt], af[0], b2);
                    mma_tf32(acc[1][nt], af[1], b2);
                }
            }
        }
        __syncthreads();
    }
}

__device__ __forceinline__ void store_direct(float* __restrict__ g, long row0,
                                             float acc[2][4][4], int tid) {
    const int lane = tid & 31, w = tid >> 5;
    const int mg = w & 1, ng = w >> 1;
    const int qr = lane >> 2, qc = lane & 3;
#pragma unroll
    for (int mt = 0; mt < 2; mt++) {
        long r = row0 + (mg * 2 + mt) * 16 + qr;
#pragma unroll
        for (int nt = 0; nt < 4; nt++) {
            int c = (ng * 4 + nt) * 8 + qc * 2;
            float2 a0; a0.x = to_tf32(acc[mt][nt][0]); a0.y = to_tf32(acc[mt][nt][1]);
            float2 a1; a1.x = to_tf32(acc[mt][nt][2]); a1.y = to_tf32(acc[mt][nt][3]);
            *(float2*)(g + (size_t)r * 128 + c) = a0;
            *(float2*)(g + (size_t)(r + 8) * 128 + c) = a1;
        }
    }
}

// ------------------- kernel 0: pack weights to fragment order (tf32) --------
// packed layout per 128x128 matrix: 4 chunks of 4096 floats; chunk kc holds
// k rows [kc*32, kc*32+32). within chunk: [ks2][n][qc][e] with
// k = kc*32 + ks2*16 + qc + (e&1)*4 + (e>>1)*8
__global__ void k_prep(const float* __restrict__ e_w, const float* __restrict__ wq,
                       const float* __restrict__ wk, const float* __restrict__ wv,
                       const float* __restrict__ wq_src, const float* __restrict__ afc_w,
                       const float* __restrict__ f_w1, const float* __restrict__ f_w2)
{
    int i = blockIdx.x * 256 + threadIdx.x;
    if (i >= W_TOT) return;
    const float* src; int rel; int ldw = 128; int kbase = 0; int nbase = 0;
    if      (i < W_Q)   { src = e_w;    rel = i - W_EW; }
    else if (i < W_K)   { src = wq;     rel = i - W_Q; }
    else if (i < W_V)   { src = wk;     rel = i - W_K; }
    else if (i < W_QS)  { src = wv;     rel = i - W_V; }
    else if (i < W_AFC) { src = wq_src; rel = i - W_QS; }
    else if (i < W_F1)  { src = afc_w;  rel = i - W_AFC; }
    else if (i < W_F2)  { src = f_w1;   rel = i - W_F1;
                          int c = rel / 16384; rel -= c * 16384; ldw = 512; nbase = c * 128; }
    else                { src = f_w2;   rel = i - W_F2;
                          int c = rel / 16384; rel -= c * 16384; kbase = c * 128; }
    int kc = rel >> 12;
    int within = rel & 4095;
    int ks2 = within >> 11;
    int remn = within & 2047;
    int n = remn >> 4;
    int rem2 = remn & 15;
    int qc = rem2 >> 2;
    int e = rem2 & 3;
    int k = kc * 32 + ks2 * 16 + qc + (e & 1) * 4 + (e >> 1) * 8;
    g_wbuf[i] = to_tf32(src[(size_t)(kbase + k) * ldw + nbase + n]);
}

// ------------------- kernel 1: z + qkv fused (M=64 tiles) -------------------
__global__ __launch_bounds__(NT, 2)
void k_zqkv(const float* __restrict__ nh, const float* __restrict__ t,
            const float* __restrict__ t_now, const float* __restrict__ ef,
            const float* __restrict__ bfreq, const float* __restrict__ phase,
            const float* __restrict__ e_b, long totrows)
{
    extern __shared__ float sm[];
    float* sA = sm;
    float* sZ = sm + 64 * LDA;
    float* sW = sZ + 64 * LDA;
    const int tid = threadIdx.x;
    const long row0 = (long)blockIdx.x * 64;
    const int rv = (int)min((long)64, totrows - row0);

#pragma unroll
    for (int j = 0; j < 8; j++) {
        int idx = tid + j * NT;
        int r = idx >> 5;
        int c4 = (idx & 31) << 2;
        float4 v = make_float4(0.f, 0.f, 0.f, 0.f);
        if (r < rv) v = *(const float4*)(ef + (size_t)(row0 + r) * 128 + c4);
        float4 o;
        o.x = to_tf32(v.x); o.y = to_tf32(v.y); o.z = to_tf32(v.z); o.w = to_tf32(v.w);
        *(float4*)(sA + r * LDA + c4) = o;
    }
    __syncthreads();

    float acc[2][4][4];
    ACC_ZERO2(acc);
    gemm128p(acc, sA, g_wbuf + W_EW, sW, tid);

    const float tn = t_now[0];
    const int lane = tid & 31, w = tid >> 5;
    const int mg = w & 1, ng = w >> 1;
    const int qr = lane >> 2, qc = lane & 3;
#pragma unroll
    for (int mt = 0; mt < 2; mt++) {
        int lr0 = (mg * 2 + mt) * 16 + qr;
#pragma unroll
        for (int hh = 0; hh < 2; hh++) {
            int lr = lr0 + hh * 8;
            long gr = row0 + lr;
            bool ok = (lr < rv);
            float tv = ok ? t[gr] : 0.f;
#pragma unroll
            for (int nt = 0; nt < 4; nt++) {
                int c = (ng * 4 + nt) * 8 + qc * 2;
#pragma unroll
                for (int p = 0; p < 2; p++) {
                    int cc = c + p;
                    float zv = 0.f;
                    if (ok) {
                        float g = gelu_exact(acc[mt][nt][hh * 2 + p] + e_b[cc]);
                        float te = cosf((tn - tv) * bfreq[cc] + phase[cc]);
                        zv = to_tf32(nh[(size_t)gr * 128 + cc] + g + te);
                        g_z[(size_t)gr * 128 + cc] = zv;
                    }
                    sZ[lr * LDA + cc] = zv;
                }
            }
        }
    }
    __syncthreads();

    ACC_ZERO2(acc); gemm128p(acc, sZ, g_wbuf + W_Q, sW, tid);
    if (rv == 64) store_direct(g_q, row0, acc, tid);
    else {
#pragma unroll
        for (int mt = 0; mt < 2; mt++) {
            int lr0 = (mg * 2 + mt) * 16 + qr;
#pragma unroll
            for (int hh = 0; hh < 2; hh++) {
                int lr = lr0 + hh * 8;
                if (lr < rv)
#pragma unroll
                    for (int nt = 0; nt < 4; nt++) {
                        int c = (ng * 4 + nt) * 8 + qc * 2;
                        float2 a; a.x = to_tf32(acc[mt][nt][hh*2]); a.y = to_tf32(acc[mt][nt][hh*2+1]);
                        *(float2*)(g_q + (size_t)(row0 + lr) * 128 + c) = a;
                    }
            }
        }
    }
    ACC_ZERO2(acc); gemm128p(acc, sZ, g_wbuf + W_K, sW, tid);
    if (rv == 64) store_direct(g_k, row0, acc, tid);
    ACC_ZERO2(acc); gemm128p(acc, sZ, g_wbuf + W_V, sW, tid);
    if (rv == 64) store_direct(g_v, row0, acc, tid);
}

// ------------------- kernel 2: self_q -------------------
__global__ __launch_bounds__(NT, 2)
void k_selfq(int Ntot)
{
    extern __shared__ float sm[];
    float* sA = sm;
    float* sW = sm + 64 * LDA;
    const int tid = threadIdx.x;
    const int n0 = blockIdx.x * 64;
    const int rv = min(64, Ntot - n0);
#pragma unroll
    for (int j = 0; j < 8; j++) {
        int idx = tid + j * NT;
        int r = idx >> 5;
        int c4 = (idx & 31) << 2;
        if (r < rv) cpa16(sA + r * LDA + c4, g_z + ((size_t)(n0 + r) * 20 + 19) * 128 + c4);
        else *(float4*)(sA + r * LDA + c4) = make_float4(0.f, 0.f, 0.f, 0.f);
    }
    CP_COMMIT();
    float acc[2][4][4];
    ACC_ZERO2(acc);
    gemm128p(acc, sA, g_wbuf + W_QS, sW, tid);
    const int lane = tid & 31, w = tid >> 5;
    const int mg = w & 1, ng = w >> 1;
    const int qr = lane >> 2, qc = lane & 3;
#pragma unroll
    for (int mt = 0; mt < 2; mt++) {
        int r = (mg * 2 + mt) * 16 + qr;
#pragma unroll
        for (int nt = 0; nt < 4; nt++) {
            int c = (ng * 4 + nt) * 8 + qc * 2;
#pragma unroll
            for (int hh = 0; hh < 2; hh++) {
                int rr = r + hh * 8;
                if (rr < rv) {
                    size_t go = ((size_t)(n0 + rr) * 20 + 19) * 128 + c;
                    float2 v;
                    v.x = to_tf32(acc[mt][nt][hh * 2]);
                    v.y = to_tf32(acc[mt][nt][hh * 2 + 1]);
                    *(float2*)(g_q + go) = v;
                    *(float2*)(g_k + go) = v;
                    *(float2*)(g_v + go) = v;
                }
            }
        }
    }
}

// ------------------- kernel 3: attention + attn_fc + residual + LN -> x ------
#define AHS 36
#define ARS 144
__global__ __launch_bounds__(NT, 2)
void k_attn_fc(const float* __restrict__ afc_b, const float* __restrict__ aln_g,
               const float* __restrict__ aln_b, int Ntot)
{
    extern __shared__ float sm[];
    float* sK = sm;                        // [60][144]; later aliased as sO [64][132]
    float* sV = sm + 60 * ARS;             // [60][144]; later aliased as scr
    float* sW = sm + 120 * ARS;            // 2*WCH
    const int tid = threadIdx.x;
    const int nb0 = blockIdx.x * 3;
    const int nodes_here = min(3, Ntot - nb0);
    const int rows = nodes_here * 20;
    const long row0 = (long)nb0 * 20;
    const size_t gbase = (size_t)row0 * 128;

    for (int i = tid; i < rows * 32; i += NT) {
        int r = i >> 5, c4 = (i & 31) << 2;
        int hd = c4 >> 5, ci = c4 & 31;
        *(float4*)(sK + r * ARS + hd * AHS + ci) = *(const float4*)(g_k + gbase + (size_t)r * 128 + c4);
        *(float4*)(sV + r * ARS + hd * AHS + ci) = *(const float4*)(g_v + gbase + (size_t)r * 128 + c4);
    }
    __syncthreads();

    const int node = tid / 80, h = (tid / 20) % 4, qi = tid % 20;
    const bool active = tid < nodes_here * 80;
    float oacc[32];
    if (active) {
        float qreg[32];
        const float* qp = g_q + gbase + (size_t)(node * 20 + qi) * 128 + h * 32;
#pragma unroll
        for (int j = 0; j < 8; j++) {
            float4 v = *(const float4*)(qp + j * 4);
            qreg[4*j] = v.x; qreg[4*j+1] = v.y; qreg[4*j+2] = v.z; qreg[4*j+3] = v.w;
        }
        float p[20];
#pragma unroll
        for (int ki = 0; ki < 20; ki++) {
            const float* kp = sK + (node * 20 + ki) * ARS + h * AHS;
            float s = 0.f;
#pragma unroll
            for (int j = 0; j < 8; j++) {
                float4 kv = *(const float4*)(kp + j * 4);
                s += qreg[4*j] * kv.x + qreg[4*j+1] * kv.y + qreg[4*j+2] * kv.z + qreg[4*j+3] * kv.w;
            }
            p[ki] = s * 0.17677669529663687f;
        }
        float m = p[0];
#pragma unroll
        for (int ki = 1; ki < 20; ki++) m = fmaxf(m, p[ki]);
        float ssum = 0.f;
#pragma unroll
        for (int ki = 0; ki < 20; ki++) { p[ki] = expf(p[ki] - m); ssum += p[ki]; }
        float inv = 1.f / ssum;
#pragma unroll
        for (int j = 0; j < 32; j++) oacc[j] = 0.f;
#pragma unroll
        for (int ki = 0; ki < 20; ki++) {
            float pw = p[ki] * inv;
            const float* vp = sV + (node * 20 + ki) * ARS + h * AHS;
#pragma unroll
            for (int j = 0; j < 8; j++) {
                float4 vv = *(const float4*)(vp + j * 4);
                oacc[4*j]   += pw * vv.x; oacc[4*j+1] += pw * vv.y;
                oacc[4*j+2] += pw * vv.z; oacc[4*j+3] += pw * vv.w;
            }
        }
    }
    __syncthreads();   // all K/V reads done; safe to alias

    float* sO = sK;
    if (active) {
        float* op = sO + (node * 20 + qi) * LDA + h * 32;
#pragma unroll
        for (int j = 0; j < 8; j++) {
            float4 v;
            v.x = to_tf32(oacc[4*j]);   v.y = to_tf32(oacc[4*j+1]);
            v.z = to_tf32(oacc[4*j+2]); v.w = to_tf32(oacc[4*j+3]);
            *(float4*)(op + j * 4) = v;
        }
    }
    for (int i = tid; i < (64 - rows) * LDA; i += NT) sO[rows * LDA + i] = 0.f;
    __syncthreads();

    float acc[2][4][4];
    ACC_ZERO2(acc);
    gemm128p(acc, sO, g_wbuf + W_AFC, sW, tid);

    {
        const int lane = tid & 31, w = tid >> 5;
        const int mg = w & 1, ng = w >> 1;
        const int qr = lane >> 2, qc = lane & 3;
#pragma unroll
        for (int mt = 0; mt < 2; mt++) {
            int r = (mg * 2 + mt) * 16 + qr;
#pragma unroll
            for (int nt = 0; nt < 4; nt++) {
                int c = (ng * 4 + nt) * 8 + qc * 2;
                sO[r * LDA + c]           = acc[mt][nt][0];
                sO[r * LDA + c + 1]       = acc[mt][nt][1];
                sO[(r + 8) * LDA + c]     = acc[mt][nt][2];
                sO[(r + 8) * LDA + c + 1] = acc[mt][nt][3];
            }
        }
    }
    __syncthreads();

    for (int i = tid; i < 64 * 128; i += NT) {
        int r = i >> 7, d = i & 127;
        if (r < rows) sO[r * LDA + d] += afc_b[d] + g_z[gbase + (size_t)r * 128 + d];
    }
    __syncthreads();

    float* scr = sV;
    if (tid < rows) {
        float m = 0.f;
#pragma unroll 8
        for (int dd = 0; dd < 128; dd++) m += sO[tid * LDA + ((dd + tid) & 127)];
        m *= (1.0f / 128.0f);
        float v = 0.f;
#pragma unroll 8
        for (int dd = 0; dd < 128; dd++) { float x = sO[tid * LDA + ((dd + tid) & 127)] - m; v += x * x; }
        v *= (1.0f / 128.0f);
        scr[tid] = m;
        scr[64 + tid] = rsqrtf(v + 1e-5f);
    }
    __syncthreads();
    for (int i = tid; i < 64 * 128; i += NT) {
        int r = i >> 7, d = i & 127;
        if (r < rows) {
            float y = (sO[r * LDA + d] - scr[r]) * scr[64 + r] * aln_g[d] + aln_b[d];
            g_x[gbase + (size_t)r * 128 + d] = to_tf32(y);
        }
    }
}

// ------------------- kernel 4: FFN + LN + fuse + out -------------------
__global__ __launch_bounds__(NT, 2)
void k_ffn(const float* __restrict__ f_b1, const float* __restrict__ f_b2,
           const float* __restrict__ fln_g, const float* __restrict__ fln_b,
           const float* __restrict__ f2n_w, const float* __restrict__ f2n_b,
           const float* __restrict__ oln_g, const float* __restrict__ oln_b,
           const float* __restrict__ nh, float* __restrict__ out, int Ntot)
{
    extern __shared__ float sm[];
    float* sX = sm;
    float* sH = sX + 64 * LDA;
    float* sW = sH + 64 * LDA;
    float* scr = sW + 2 * WCH;
    const int tid = threadIdx.x;
    const int nb0 = blockIdx.x * 3;
    const int nodes_here = min(3, Ntot - nb0);
    const int rows_here = nodes_here * 20;
    const long row0 = (long)nb0 * 20;

    stageActa(sX, g_x, row0, rows_here, tid);

    float x2[2][4][4];
    ACC_ZERO2(x2);
    const int lane = tid & 31, w = tid >> 5;
    const int mg = w & 1, ng = w >> 1;
    const int qr = lane >> 2, qc = lane & 3;

    for (int c = 0; c < 4; c++) {
        float acc[2][4][4];
        ACC_ZERO2(acc);
        gemm128p(acc, sX, g_wbuf + W_F1 + c * 16384, sW, tid);
#pragma unroll
        for (int mt = 0; mt < 2; mt++) {
            int r = (mg * 2 + mt) * 16 + qr;
#pragma unroll
            for (int nt = 0; nt < 4; nt++) {
                int col = (ng * 4 + nt) * 8 + qc * 2;
                float b0 = f_b1[c * 128 + col], b1 = f_b1[c * 128 + col + 1];
                sH[r * LDA + col]           = to_tf32(fmaxf(acc[mt][nt][0] + b0, 0.f));
                sH[r * LDA + col + 1]       = to_tf32(fmaxf(acc[mt][nt][1] + b1, 0.f));
                sH[(r + 8) * LDA + col]     = to_tf32(fmaxf(acc[mt][nt][2] + b0, 0.f));
                sH[(r + 8) * LDA + col + 1] = to_tf32(fmaxf(acc[mt][nt][3] + b1, 0.f));
            }
        }
        __syncthreads();
        gemm128p(x2, sH, g_wbuf + W_F2 + c * 16384, sW, tid);
    }

#pragma unroll
    for (int mt = 0; mt < 2; mt++) {
        int r = (mg * 2 + mt) * 16 + qr;
#pragma unroll
        for (int nt = 0; nt < 4; nt++) {
            int col = (ng * 4 + nt) * 8 + qc * 2;
            float b0 = f_b2[col], b1 = f_b2[col + 1];
            sH[r * LDA + col]           = x2[mt][nt][0] + b0 + sX[r * LDA + col];
            sH[r * LDA + col + 1]       = x2[mt][nt][1] + b1 + sX[r * LDA + col + 1];
            sH[(r + 8) * LDA + col]     = x2[mt][nt][2] + b0 + sX[(r + 8) * LDA + col];
            sH[(r + 8) * LDA + col + 1] = x2[mt][nt][3] + b1 + sX[(r + 8) * LDA + col + 1];
        }
    }
    __syncthreads();

    if (tid < rows_here) {
        float m = 0.f;
#pragma unroll 8
        for (int dd = 0; dd < 128; dd++) m += sH[tid * LDA + ((dd + tid) & 127)];
        m *= (1.0f / 128.0f);
        float v = 0.f;
#pragma unroll 8
        for (int dd = 0; dd < 128; dd++) { float x = sH[tid * LDA + ((dd + tid) & 127)] - m; v += x * x; }
        v *= (1.0f / 128.0f);
        scr[tid] = m;
        scr[64 + tid] = rsqrtf(v + 1e-5f);
    }
    __syncthreads();
    for (int i = tid; i < rows_here * 128; i += NT) {
        int r = i >> 7, d = i & 127;
        sH[r * LDA + d] = (sH[r * LDA + d] - scr[r]) * scr[64 + r] * fln_g[d] + fln_b[d];
    }
    __syncthreads();

    float* sNe = scr + 128;
    float* sY  = scr + 512;
    for (int i = tid; i < nodes_here * 128; i += NT) {
        int node = i >> 7, d = i & 127;
        float s = 0.f;
#pragma unroll
        for (int k = 0; k < 19; k++) s += sH[(node * 20 + k) * LDA + d];
        sNe[i] = s * (1.0f / 19.0f);
    }
    __syncthreads();
    for (int idx = tid; idx < nodes_here * 128; idx += NT) {
        int node = idx >> 7, d = idx & 127;
        const float* selfr = sH + (node * 20 + 19) * LDA;
        const float* ne = sNe + node * 128;
        float a = 0.f;
#pragma unroll 4
        for (int e = 0; e < 128; e++) a += selfr[e] * f2n_w[e * 128 + d];
#pragma unroll 4
        for (int e = 0; e < 128; e++) a += ne[e] * f2n_w[(128 + e) * 128 + d];
        float y = gelu_exact(a + f2n_b[d])
                + nh[((size_t)(nb0 + node) * 20 + 19) * 128 + d];
        sY[idx] = y;
    }
    __syncthreads();
    if (tid < nodes_here) {
        float m = 0.f;
        for (int d = 0; d < 128; d++) m += sY[tid * 128 + d];
        m *= (1.0f / 128.0f);
        float v = 0.f;
        for (int d = 0; d < 128; d++) { float x = sY[tid * 128 + d] - m; v += x * x; }
        v *= (1.0f / 128.0f);
        scr[896 + tid] = m;
        scr[900 + tid] = rsqrtf(v + 1e-5f);
    }
    __syncthreads();
    for (int idx = tid; idx < nodes_here * 128; idx += NT) {
        int node = idx >> 7, d = idx & 127;
        float y = (sY[idx] - scr[896 + node]) * scr[900 + node];
        out[(size_t)(nb0 + node) * 128 + d] = y * oln_g[d] + oln_b[d];
    }
}

// ------------------- launch -------------------
#define SM_ZQKV ((2 * 64 * LDA + 2 * WCH) * 4)
#define SM_AB   ((64 * LDA + 2 * WCH) * 4)
#define SM_FUSE ((120 * ARS + 2 * WCH) * 4)
#define SM_F    ((2 * 64 * LDA + 2 * WCH + 1024) * 4)

extern "C" void kernel_launch(void* const* d_in, const int* in_sizes, int n_in,
                              void* d_out, int out_size) {
    (void)n_in; (void)out_size;
    const float* nh      = (const float*)d_in[0];
    const float* t       = (const float*)d_in[1];
    const float* t_now   = (const float*)d_in[2];
    const float* ef      = (const float*)d_in[3];
    const float* bfreq   = (const float*)d_in[4];
    const float* phase   = (const float*)d_in[5];
    const float* e_w     = (const float*)d_in[6];
    const float* e_b     = (const float*)d_in[7];
    const float* wq      = (const float*)d_in[8];
    const float* wk      = (const float*)d_in[9];
    const float* wv      = (const float*)d_in[10];
    const float* wq_src  = (const float*)d_in[11];
    const float* afc_w   = (const float*)d_in[12];
    const float* afc_b   = (const float*)d_in[13];
    const float* aln_g   = (const float*)d_in[14];
    const float* aln_b   = (const float*)d_in[15];
    const float* f_w1    = (const float*)d_in[16];
    const float* f_b1    = (const float*)d_in[17];
    const float* f_w2    = (const float*)d_in[18];
    const float* f_b2    = (const float*)d_in[19];
    const float* fln_g   = (const float*)d_in[20];
    const float* fln_b   = (const float*)d_in[21];
    const float* f2n_w   = (const float*)d_in[22];
    const float* f2n_b   = (const float*)d_in[23];
    const float* oln_g   = (const float*)d_in[24];
    const float* oln_b   = (const float*)d_in[25];
    float* out = (float*)d_out;

    const int N = in_sizes[0] / 2560;
    const long totrows = (long)N * 20;
    const int gM = (int)((totrows + 63) / 64);

    cudaFuncSetAttribute(k_zqkv,    cudaFuncAttributeMaxDynamicSharedMemorySize, SM_ZQKV);
    cudaFuncSetAttribute(k_selfq,   cudaFuncAttributeMaxDynamicSharedMemorySize, SM_AB);
    cudaFuncSetAttribute(k_attn_fc, cudaFuncAttributeMaxDynamicSharedMemorySize, SM_FUSE);
    cudaFuncSetAttribute(k_ffn,     cudaFuncAttributeMaxDynamicSharedMemorySize, SM_F);

    k_prep<<<(W_TOT + 255) / 256, 256>>>(e_w, wq, wk, wv, wq_src, afc_w, f_w1, f_w2);
    k_zqkv<<<gM, NT, SM_ZQKV>>>(nh, t, t_now, ef, bfreq, phase, e_b, totrows);
    k_selfq<<<(N + 63) / 64, NT, SM_AB>>>(N);
    k_attn_fc<<<(N + 2) / 3, NT, SM_FUSE>>>(afc_b, aln_g, aln_b, N);
    k_ffn<<<(N + 2) / 3, NT, SM_F>>>(f_b1, f_b2, fln_g, fln_b,
                                     f2n_w, f2n_b, oln_g, oln_b, nh, out, N);
}